// round 1
// baseline (speedup 1.0000x reference)
#include <cuda_runtime.h>

// PatchEmbedding: x(1,3,384,384) f32, W(768,12), b(768), positions(768,146689)
// out(1,768,146689) f32:
//   out[e,l] = b[e] + positions[e,l] + sum_d patch[d,l] * W[e,d]
// patch[d,l], d = c*4 + i*2 + j, l = r*383 + col, value = x[c, r+i, col+j]

#define IMG      384
#define LW       383                 // output spatial width (384 - 2 + 1)
#define L_TOTAL  (383 * 383)         // 146689
#define EMB      768
#define PD       12                  // patch_dim = 3*2*2

#define TPB      256                 // threads per block
#define LPT      4                   // l-values per thread (strided by TPB)
#define L_TILE   (TPB * LPT)         // 1024 l per block
#define E_TILE   96                  // embedding rows per block (768/96 = 8 y-blocks)

__global__ __launch_bounds__(TPB, 4)
void patch_embed_kernel(const float* __restrict__ x,
                        const float* __restrict__ W,
                        const float* __restrict__ b,
                        const float* __restrict__ pos,
                        float* __restrict__ out) {
    __shared__ float sW[E_TILE * PD];   // 4.5 KB
    __shared__ float sB[E_TILE];

    const int e0 = blockIdx.y * E_TILE;

    // Stage W tile + b tile into shared memory.
    for (int i = threadIdx.x; i < E_TILE * PD; i += TPB)
        sW[i] = W[e0 * PD + i];
    if (threadIdx.x < E_TILE)
        sB[threadIdx.x] = b[e0 + threadIdx.x];

    // Gather this thread's LPT patch vectors ONCE (12 x-loads per l, all L2/L1 hits;
    // reused across the full E_TILE loop -> gather cost amortized 96x).
    const int lbase = blockIdx.x * L_TILE + threadIdx.x;

    float p[LPT][PD];
    int   lidx[LPT];
    bool  valid[LPT];

    #pragma unroll
    for (int k = 0; k < LPT; k++) {
        int l = lbase + k * TPB;
        lidx[k]  = l;
        valid[k] = (l < L_TOTAL);
        int ls  = valid[k] ? l : 0;
        int r   = ls / LW;
        int col = ls - r * LW;
        const float* xp = x + r * IMG + col;
        #pragma unroll
        for (int c = 0; c < 3; c++) {
            #pragma unroll
            for (int i = 0; i < 2; i++) {
                #pragma unroll
                for (int j = 0; j < 2; j++) {
                    p[k][c * 4 + i * 2 + j] = xp[c * IMG * IMG + i * IMG + j];
                }
            }
        }
    }

    __syncthreads();

    // Stream over embedding rows: W row broadcast from smem into registers,
    // positions streamed from HBM, fused add, store.
    for (int ee = 0; ee < E_TILE; ee++) {
        const int e = e0 + ee;
        float wv[PD];
        #pragma unroll
        for (int d = 0; d < PD; d++)
            wv[d] = sW[ee * PD + d];
        const float bb = sB[ee];

        const float* __restrict__ posrow = pos + (size_t)e * L_TOTAL;
        float*       __restrict__ outrow = out + (size_t)e * L_TOTAL;

        #pragma unroll
        for (int k = 0; k < LPT; k++) {
            if (valid[k]) {
                float acc = bb;
                #pragma unroll
                for (int d = 0; d < PD; d++)
                    acc = fmaf(p[k][d], wv[d], acc);
                outrow[lidx[k]] = acc + posrow[lidx[k]];
            }
        }
    }
}

extern "C" void kernel_launch(void* const* d_in, const int* in_sizes, int n_in,
                              void* d_out, int out_size) {
    const float* x   = (const float*)d_in[0];
    const float* W   = (const float*)d_in[1];
    const float* b   = (const float*)d_in[2];
    const float* pos = (const float*)d_in[3];
    float* out = (float*)d_out;

    dim3 grid((L_TOTAL + L_TILE - 1) / L_TILE,   // 144
              EMB / E_TILE,                      // 8
              1);
    patch_embed_kernel<<<grid, TPB>>>(x, W, b, pos, out);
}

// round 2
// speedup vs baseline: 1.0930x; 1.0930x over previous
#include <cuda_runtime.h>

// PatchEmbedding: x(1,3,384,384) f32, W(768,12), b(768), positions(768,146689)
// out[e,l] = b[e] + positions[e,l] + sum_d patch[d,l] * W[e,d]
// d = c*4 + i*2 + j, l = r*383 + col, patch value = x[c, r+i, col+j]

#define IMG      384
#define LW       383
#define L_TOTAL  (383 * 383)         // 146689
#define EMB      768
#define PD       12

#define TPB      256
#define LPT      2                   // l-values per thread
#define L_TILE   (TPB * LPT)         // 512
#define E_TILE   64                  // 768/64 = 12 y-blocks

__global__ __launch_bounds__(TPB, 5)   // cap regs ~51 -> 40 warps/SM
void patch_embed_kernel(const float* __restrict__ x,
                        const float* __restrict__ W,
                        const float* __restrict__ b,
                        const float* __restrict__ pos,
                        float* __restrict__ out) {
    __shared__ float4 sW[E_TILE * 3];   // 12 floats per e-row = 3 float4 (48B stride, 16B aligned)
    __shared__ float  sB[E_TILE];

    const int e0 = blockIdx.y * E_TILE;

    // Stage W tile (vectorized: W row stride 48B is 16B-aligned) + b tile.
    {
        const float4* Wg = (const float4*)(W + (size_t)e0 * PD);
        for (int i = threadIdx.x; i < E_TILE * 3; i += TPB)
            sW[i] = Wg[i];
        if (threadIdx.x < E_TILE)
            sB[threadIdx.x] = b[e0 + threadIdx.x];
    }

    // Gather this thread's LPT patch vectors once (x is 1.7MB -> L2/L1 hits,
    // amortized E_TILE times).
    const int lbase = blockIdx.x * L_TILE + threadIdx.x;

    float p[LPT][PD];
    bool  valid[LPT];

    #pragma unroll
    for (int k = 0; k < LPT; k++) {
        const int l = lbase + k * TPB;
        valid[k] = (l < L_TOTAL);
        const int ls  = valid[k] ? l : 0;
        const int r   = ls / LW;
        const int col = ls - r * LW;
        const float* xp = x + r * IMG + col;
        #pragma unroll
        for (int c = 0; c < 3; c++) {
            #pragma unroll
            for (int i = 0; i < 2; i++) {
                #pragma unroll
                for (int j = 0; j < 2; j++) {
                    p[k][c * 4 + i * 2 + j] = xp[c * IMG * IMG + i * IMG + j];
                }
            }
        }
    }

    __syncthreads();

    // Stream over embedding rows. Unroll 4 so ptxas front-batches the pos
    // loads (MLP ~8 per warp) while FFMA chains of the previous sub-iters hide
    // the DRAM latency.
    #pragma unroll 4
    for (int ee = 0; ee < E_TILE; ee++) {
        const float4 w0 = sW[ee * 3 + 0];
        const float4 w1 = sW[ee * 3 + 1];
        const float4 w2 = sW[ee * 3 + 2];
        const float  bb = sB[ee];

        const size_t rowbase = (size_t)(e0 + ee) * L_TOTAL + lbase;

        // Issue all pos loads for this ee first (independent of the FMA work).
        float pv[LPT];
        #pragma unroll
        for (int k = 0; k < LPT; k++)
            if (valid[k]) pv[k] = pos[rowbase + k * TPB];

        #pragma unroll
        for (int k = 0; k < LPT; k++) {
            if (valid[k]) {
                // Two depth-6 FMA chains instead of one depth-12 chain.
                float c0 = p[k][0] * w0.x;
                float c1 = p[k][1] * w0.y;
                c0 = fmaf(p[k][2],  w0.z, c0);
                c1 = fmaf(p[k][3],  w0.w, c1);
                c0 = fmaf(p[k][4],  w1.x, c0);
                c1 = fmaf(p[k][5],  w1.y, c1);
                c0 = fmaf(p[k][6],  w1.z, c0);
                c1 = fmaf(p[k][7],  w1.w, c1);
                c0 = fmaf(p[k][8],  w2.x, c0);
                c1 = fmaf(p[k][9],  w2.y, c1);
                c0 = fmaf(p[k][10], w2.z, c0);
                c1 = fmaf(p[k][11], w2.w, c1);
                out[rowbase + k * TPB] = (bb + pv[k]) + (c0 + c1);
            }
        }
    }
}

extern "C" void kernel_launch(void* const* d_in, const int* in_sizes, int n_in,
                              void* d_out, int out_size) {
    const float* x   = (const float*)d_in[0];
    const float* W   = (const float*)d_in[1];
    const float* b   = (const float*)d_in[2];
    const float* pos = (const float*)d_in[3];
    float* out = (float*)d_out;

    dim3 grid((L_TOTAL + L_TILE - 1) / L_TILE,   // 287
              EMB / E_TILE,                      // 12
              1);
    patch_embed_kernel<<<grid, TPB>>>(x, W, b, pos, out);
}

// round 3
// speedup vs baseline: 1.5533x; 1.4211x over previous
#include <cuda_runtime.h>

// PatchEmbedding: x(1,3,384,384) f32, W(768,12), b(768), positions(768,146689)
// out[e,l] = b[e] + positions[e,l] + sum_d patch[d,l] * W[e,d]
// d = c*4 + i*2 + j, l = r*383 + col, patch value = x[c, r+i, col+j]

#define IMG      384
#define LW       383
#define L_TOTAL  (383 * 383)         // 146689
#define EMB      768
#define PD       12

#define TPB      256
#define LPT      2                   // l-values per thread
#define L_TILE   (TPB * LPT)         // 512
#define E_TILE   64                  // 768/64 = 12 y-blocks
#define CH       4                   // ee per prefetch chunk (8 LDGs in flight)
#define NCH      (E_TILE / CH)       // 16

__device__ __forceinline__ void gather_patch(const float* __restrict__ x,
                                             int l, float* p) {
    const int r   = l / LW;
    const int col = l - r * LW;
    const float* xp = x + r * IMG + col;
    #pragma unroll
    for (int c = 0; c < 3; c++)
        #pragma unroll
        for (int i = 0; i < 2; i++)
            #pragma unroll
            for (int j = 0; j < 2; j++)
                p[c * 4 + i * 2 + j] = xp[c * IMG * IMG + i * IMG + j];
}

__device__ __forceinline__ float dot12(const float* p,
                                       float4 w0, float4 w1, float4 w2) {
    // Two depth-6 chains.
    float c0 = p[0] * w0.x;
    float c1 = p[1] * w0.y;
    c0 = fmaf(p[2],  w0.z, c0);  c1 = fmaf(p[3],  w0.w, c1);
    c0 = fmaf(p[4],  w1.x, c0);  c1 = fmaf(p[5],  w1.y, c1);
    c0 = fmaf(p[6],  w1.z, c0);  c1 = fmaf(p[7],  w1.w, c1);
    c0 = fmaf(p[8],  w2.x, c0);  c1 = fmaf(p[9],  w2.y, c1);
    c0 = fmaf(p[10], w2.z, c0);  c1 = fmaf(p[11], w2.w, c1);
    return c0 + c1;
}

__global__ __launch_bounds__(TPB, 4)
void patch_embed_kernel(const float* __restrict__ x,
                        const float* __restrict__ W,
                        const float* __restrict__ b,
                        const float* __restrict__ pos,
                        float* __restrict__ out) {
    __shared__ float4 sW[E_TILE * 3];
    __shared__ float  sB[E_TILE];

    const int e0 = blockIdx.y * E_TILE;

    {
        const float4* Wg = (const float4*)(W + (size_t)e0 * PD);
        for (int i = threadIdx.x; i < E_TILE * 3; i += TPB)
            sW[i] = Wg[i];
        if (threadIdx.x < E_TILE)
            sB[threadIdx.x] = b[e0 + threadIdx.x];
    }

    const int lbase = blockIdx.x * L_TILE + threadIdx.x;
    const bool full_block = (blockIdx.x + 1) * L_TILE <= L_TOTAL;

    if (full_block) {
        // ---- fast path: no bounds checks anywhere ----
        float p[LPT][PD];
        #pragma unroll
        for (int k = 0; k < LPT; k++)
            gather_patch(x, lbase + k * TPB, p[k]);

        __syncthreads();

        const float* __restrict__ posrow = pos + (size_t)e0 * L_TOTAL + lbase;
        float*       __restrict__ outrow = out + (size_t)e0 * L_TOTAL + lbase;

        // Double-buffered prefetch: 8 independent pos loads always in flight.
        float pv[2][CH * LPT];

        #pragma unroll
        for (int j = 0; j < CH; j++)
            #pragma unroll
            for (int k = 0; k < LPT; k++)
                pv[0][j * LPT + k] = posrow[j * L_TOTAL + k * TPB];

        #pragma unroll 2
        for (int cc = 0; cc < NCH; cc++) {
            const int cur = cc & 1;

            if (cc + 1 < NCH) {
                const int eb = (cc + 1) * CH;
                #pragma unroll
                for (int j = 0; j < CH; j++)
                    #pragma unroll
                    for (int k = 0; k < LPT; k++)
                        pv[cur ^ 1][j * LPT + k] =
                            posrow[(eb + j) * L_TOTAL + k * TPB];
            }

            #pragma unroll
            for (int j = 0; j < CH; j++) {
                const int ee = cc * CH + j;
                const float4 w0 = sW[ee * 3 + 0];
                const float4 w1 = sW[ee * 3 + 1];
                const float4 w2 = sW[ee * 3 + 2];
                const float  bb = sB[ee];
                #pragma unroll
                for (int k = 0; k < LPT; k++) {
                    const float d = dot12(p[k], w0, w1, w2);
                    outrow[ee * L_TOTAL + k * TPB] =
                        (bb + pv[cur][j * LPT + k]) + d;
                }
            }
        }
    } else {
        // ---- masked tail path (1 of 287 l-blocks) ----
        float p[LPT][PD];
        bool  valid[LPT];
        #pragma unroll
        for (int k = 0; k < LPT; k++) {
            const int l = lbase + k * TPB;
            valid[k] = (l < L_TOTAL);
            gather_patch(x, valid[k] ? l : 0, p[k]);
        }

        __syncthreads();

        const float* __restrict__ posrow = pos + (size_t)e0 * L_TOTAL + lbase;
        float*       __restrict__ outrow = out + (size_t)e0 * L_TOTAL + lbase;

        for (int ee = 0; ee < E_TILE; ee++) {
            const float4 w0 = sW[ee * 3 + 0];
            const float4 w1 = sW[ee * 3 + 1];
            const float4 w2 = sW[ee * 3 + 2];
            const float  bb = sB[ee];
            float pvv[LPT];
            #pragma unroll
            for (int k = 0; k < LPT; k++)
                if (valid[k]) pvv[k] = posrow[ee * L_TOTAL + k * TPB];
            #pragma unroll
            for (int k = 0; k < LPT; k++) {
                if (valid[k]) {
                    const float d = dot12(p[k], w0, w1, w2);
                    outrow[ee * L_TOTAL + k * TPB] = (bb + pvv[k]) + d;
                }
            }
        }
    }
}

extern "C" void kernel_launch(void* const* d_in, const int* in_sizes, int n_in,
                              void* d_out, int out_size) {
    const float* x   = (const float*)d_in[0];
    const float* W   = (const float*)d_in[1];
    const float* b   = (const float*)d_in[2];
    const float* pos = (const float*)d_in[3];
    float* out = (float*)d_out;

    dim3 grid((L_TOTAL + L_TILE - 1) / L_TILE,   // 287
              EMB / E_TILE,                      // 12
              1);
    patch_embed_kernel<<<grid, TPB>>>(x, W, b, pos, out);
}